// round 4
// baseline (speedup 1.0000x reference)
#include <cuda_runtime.h>
#include <cstdint>

// ---------------------------------------------------------------------------
// PointTransformerLayer: B=1, N=50000, K=16, DIM=64, fp32.
// fp32x2 packed FFMA; lane j owns dims (j, j+32). 8 warps/block, KB=2
// k-blocking to halve smem weight traffic, -W_psi trick folds beta
// accumulation into one register, cp.async pipelined neighbour features,
// atomic work stealing over P=8 point groups.
// ---------------------------------------------------------------------------

constexpr int KNB     = 16;
constexpr int DIM     = 64;
constexpr int P       = 8;
constexpr int WARPS   = 8;
constexpr int THREADS = WARPS * 32;
constexpr int KB      = 2;
constexpr int NCHUNK  = KNB / KB;   // 8

// per-warp floats: nfslot[2][1024] betab[1024] fbuf[512] dbuf4[128]f4 nxb[384] pxb[32]
constexpr int WARP_FLTS  = 2048 + 1024 + 512 + 512 + 384 + 32;        // 4512
constexpr int HDR_BYTES  = 2048 * 16 + 2048 * 8 * 2 + (96 + 128) * 8; // 67328
constexpr int SMEM_BYTES = HDR_BYTES + WARPS * WARP_FLTS * 4;         // 211712

__device__ int g_work;

__device__ __forceinline__ float2 ffma2(float2 a, float2 b, float2 c) {
    unsigned long long ra = *reinterpret_cast<unsigned long long*>(&a);
    unsigned long long rb = *reinterpret_cast<unsigned long long*>(&b);
    unsigned long long rc = *reinterpret_cast<unsigned long long*>(&c);
    unsigned long long rd;
    asm("fma.rn.f32x2 %0, %1, %2, %3;" : "=l"(rd) : "l"(ra), "l"(rb), "l"(rc));
    return *reinterpret_cast<float2*>(&rd);
}
__device__ __forceinline__ float2 add2(float2 a, float2 b) {
    unsigned long long ra = *reinterpret_cast<unsigned long long*>(&a);
    unsigned long long rb = *reinterpret_cast<unsigned long long*>(&b);
    unsigned long long rd;
    asm("add.rn.f32x2 %0, %1, %2;" : "=l"(rd) : "l"(ra), "l"(rb));
    return *reinterpret_cast<float2*>(&rd);
}
__device__ __forceinline__ float2 mul2(float2 a, float2 b) {
    unsigned long long ra = *reinterpret_cast<unsigned long long*>(&a);
    unsigned long long rb = *reinterpret_cast<unsigned long long*>(&b);
    unsigned long long rd;
    asm("mul.rn.f32x2 %0, %1, %2;" : "=l"(rd) : "l"(ra), "l"(rb));
    return *reinterpret_cast<float2*>(&rd);
}
__device__ __forceinline__ float2 dup2(float s) { return make_float2(s, s); }

__device__ __forceinline__ void cp16(unsigned dst, const void* src) {
    asm volatile("cp.async.cg.shared.global [%0], [%1], 16;\n" :: "r"(dst), "l"(src));
}
__device__ __forceinline__ void cp_commit() {
    asm volatile("cp.async.commit_group;\n");
}
template <int NN>
__device__ __forceinline__ void cp_wait() {
    asm volatile("cp.async.wait_group %0;\n" :: "n"(NN));
}

__global__ void __launch_bounds__(THREADS, 1)
pt_layer_kernel(const float* __restrict__ pxyz,  const float* __restrict__ pfeat,
                const float* __restrict__ nxyz,  const float* __restrict__ nfeat,
                const float* __restrict__ Wphi,  const float* __restrict__ bphi,
                const float* __restrict__ Wpsi,  const float* __restrict__ bpsi,
                const float* __restrict__ Wal,   const float* __restrict__ bal,
                const float* __restrict__ Wga,   const float* __restrict__ bga,
                const float* __restrict__ Wd1,   const float* __restrict__ bd1,
                const float* __restrict__ Wd2,   const float* __restrict__ bd2,
                float* __restrict__ out, int N)
{
    extern __shared__ char smraw[];
    float4* WPA4  = reinterpret_cast<float4*>(smraw);      // [64][32] (-wpsi.j, -wpsi.j32, wal.j, wal.j32)
    float2* Wphi2 = reinterpret_cast<float2*>(WPA4 + 2048);
    float2* Wg2   = Wphi2 + 2048;
    float2* M2    = Wg2   + 2048;   // [3][32]
    float2* cvec2 = M2    + 96;
    float2* bb2   = cvec2 + 32;     // b_phi - b_psi
    float2* ba2   = bb2   + 32;
    float2* bg2   = ba2   + 32;

    const int tid  = threadIdx.x;
    const int lane = tid & 31;
    const int warp = tid >> 5;

    float*  warpf  = reinterpret_cast<float*>(bg2 + 32) + warp * WARP_FLTS;
    float*  nfslot = warpf;              // [2][1024]  slot: [(p*2+ko)*64 + c]
    float*  betab  = warpf + 2048;       // [16][64]
    float*  fbuf   = warpf + 3072;       // [8][64]
    float4* dbuf4  = reinterpret_cast<float4*>(warpf + 3584); // [8][16] (dx,dy,dz,0)
    float*  nxb    = warpf + 4096;       // [8][16][3]
    float*  pxb    = warpf + 4480;       // [8][3] + pad

    const unsigned nf_a = (unsigned)__cvta_generic_to_shared(nfslot);
    const unsigned fb_a = (unsigned)__cvta_generic_to_shared(fbuf);
    const unsigned nx_a = (unsigned)__cvta_generic_to_shared(nxb);
    const unsigned px_a = (unsigned)__cvta_generic_to_shared(pxb);

    // ---- stage weights ----
    for (int idx = tid; idx < 2048; idx += THREADS) {
        int c = idx >> 5, j = idx & 31;
        WPA4[idx]  = make_float4(-Wpsi[c * 64 + j], -Wpsi[c * 64 + j + 32],
                                  Wal [c * 64 + j],  Wal [c * 64 + j + 32]);
        Wphi2[idx] = make_float2(Wphi[c * 64 + j], Wphi[c * 64 + j + 32]);
        Wg2[idx]   = make_float2(Wga [c * 64 + j], Wga [c * 64 + j + 32]);
    }
    for (int idx = tid; idx < 96; idx += THREADS) {
        int r = idx >> 5, j = idx & 31;
        float sx = 0.f, sy = 0.f;
        for (int c = 0; c < 64; c++) {
            float w1 = Wd1[r * 64 + c];
            sx += w1 * Wd2[c * 64 + j];
            sy += w1 * Wd2[c * 64 + j + 32];
        }
        M2[idx] = make_float2(sx, sy);
    }
    if (tid < 32) {
        int j = tid;
        float sx = bd2[j], sy = bd2[j + 32];
        for (int c = 0; c < 64; c++) {
            float b = bd1[c];
            sx += b * Wd2[c * 64 + j];
            sy += b * Wd2[c * 64 + j + 32];
        }
        cvec2[j] = make_float2(sx, sy);
        bb2[j]   = make_float2(bphi[j] - bpsi[j], bphi[j + 32] - bpsi[j + 32]);
        ba2[j]   = make_float2(bal[j], bal[j + 32]);
        bg2[j]   = make_float2(bga[j], bga[j + 32]);
    }
    __syncthreads();

    const int j = lane;
    const float2 m0 = M2[j], m1 = M2[32 + j], m2 = M2[64 + j];
    const float2 cv = cvec2[j], bb = bb2[j], ba = ba2[j], bg = bg2[j];

    const int ngroups = (N + P - 1) / P;

    for (;;) {
        int grp;
        if (lane == 0) grp = atomicAdd(&g_work, 1);
        grp = __shfl_sync(0xffffffffu, grp, 0);
        if (grp >= ngroups) break;

        const int base = grp * P;
        const int npts = min(P, N - base);
        const float* nsrc = nfeat + (size_t)base * (KNB * DIM);
        const bool full = (npts == P);

        if (full) {
            const float* fsrc = pfeat + (size_t)base * DIM;
            #pragma unroll
            for (int r = 0; r < 4; r++) { int i = lane + r * 32; cp16(fb_a + i * 16, fsrc + i * 4); }
            if (lane < 6) cp16(px_a + lane * 16, pxyz + (size_t)base * 3 + lane * 4);
            const float* nxsrc = nxyz + (size_t)base * 48;
            #pragma unroll
            for (int r = 0; r < 3; r++) { int i = lane + r * 32; cp16(nx_a + i * 16, nxsrc + i * 4); }
            cp_commit();
            // chunk 0 and chunk 1 (each: 2 k's x 8 pts x 64)
            #pragma unroll
            for (int r = 0; r < 8; r++) {
                int i = lane + r * 32; int p = i >> 5, rem = i & 31;
                cp16(nf_a + i * 16, nsrc + ((size_t)p * KNB + 0) * DIM + rem * 4);
            }
            cp_commit();
            #pragma unroll
            for (int r = 0; r < 8; r++) {
                int i = lane + r * 32; int p = i >> 5, rem = i & 31;
                cp16(nf_a + 4096 + i * 16, nsrc + ((size_t)p * KNB + KB) * DIM + rem * 4);
            }
            cp_commit();
            cp_wait<2>();           // fbuf / pxb / nxb ready
        } else {
            for (int i = lane; i < P * DIM; i += 32)
                fbuf[i] = (i < npts * DIM) ? pfeat[(size_t)base * DIM + i] : 0.f;
            for (int i = lane; i < 32; i += 32)
                pxb[i] = (i < npts * 3) ? pxyz[(size_t)base * 3 + i] : 0.f;
            for (int i = lane; i < P * KNB * 3; i += 32)
                nxb[i] = (i < npts * 48) ? nxyz[(size_t)base * 48 + i] : 0.f;
        }
        __syncwarp();

        // ---- dbuf4: (px - nx, pad) per (p,k) ----
        #pragma unroll
        for (int r = 0; r < 4; r++) {
            int i = lane + r * 32; int p = i >> 4, k = i & 15;
            float dx = pxb[p * 3 + 0] - nxb[(p * 16 + k) * 3 + 0];
            float dy = pxb[p * 3 + 1] - nxb[(p * 16 + k) * 3 + 1];
            float dz = pxb[p * 3 + 2] - nxb[(p * 16 + k) * 3 + 2];
            dbuf4[i] = make_float4(dx, dy, dz, 0.f);
        }
        __syncwarp();

        // ---- phi (includes b_phi - b_psi) ----
        float2 phi[P], o[P];
        #pragma unroll
        for (int p = 0; p < P; p++) { phi[p] = bb; o[p] = make_float2(0.f, 0.f); }
        #pragma unroll 4
        for (int c4 = 0; c4 < 16; c4++) {
            const int cb = c4 * 4;
            float2 w0 = Wphi2[(cb + 0) * 32 + j];
            float2 w1 = Wphi2[(cb + 1) * 32 + j];
            float2 w2 = Wphi2[(cb + 2) * 32 + j];
            float2 w3 = Wphi2[(cb + 3) * 32 + j];
            #pragma unroll
            for (int p = 0; p < P; p++) {
                float4 fv = *reinterpret_cast<const float4*>(fbuf + p * 64 + cb);
                phi[p] = ffma2(dup2(fv.x), w0, phi[p]);
                phi[p] = ffma2(dup2(fv.y), w1, phi[p]);
                phi[p] = ffma2(dup2(fv.z), w2, phi[p]);
                phi[p] = ffma2(dup2(fv.w), w3, phi[p]);
            }
        }

        // ---- k-chunk loop (KB=2 neighbours per iteration) ----
        #pragma unroll 1
        for (int t = 0; t < NCHUNK; t++) {
            float* slot = nfslot + (t & 1) * 1024;
            if (full) {
                if (t < NCHUNK - 1) cp_wait<1>(); else cp_wait<0>();
            } else {
                for (int i = lane; i < KB * P * DIM; i += 32) {
                    int p = i >> 7, rem = i & 127; int ko = rem >> 6, c = rem & 63;
                    slot[i] = (p < npts)
                        ? nfeat[(((size_t)(base + p)) * KNB + t * KB + ko) * DIM + c] : 0.f;
                }
            }
            __syncwarp();

            // beta/alpha accumulators seeded with phi+delta / b_alpha+delta
            float2 bt[P][KB], al[P][KB];
            #pragma unroll
            for (int p = 0; p < P; p++) {
                #pragma unroll
                for (int ko = 0; ko < KB; ko++) {
                    float4 dv = dbuf4[p * 16 + t * KB + ko];
                    float2 d = cv;
                    d = ffma2(dup2(dv.x), m0, d);
                    d = ffma2(dup2(dv.y), m1, d);
                    d = ffma2(dup2(dv.z), m2, d);
                    d.x = fmaxf(d.x, 0.f); d.y = fmaxf(d.y, 0.f);
                    bt[p][ko] = add2(phi[p], d);
                    al[p][ko] = add2(ba, d);
                }
            }

            // fused (-psi)+alpha GEMMs: one weight pass serves 16 (p,k) pairs
            #pragma unroll 4
            for (int c4 = 0; c4 < 16; c4++) {
                const int cb = c4 * 4;
                float4 wv0 = WPA4[(cb + 0) * 32 + j];
                float4 wv1 = WPA4[(cb + 1) * 32 + j];
                float4 wv2 = WPA4[(cb + 2) * 32 + j];
                float4 wv3 = WPA4[(cb + 3) * 32 + j];
                #pragma unroll
                for (int p = 0; p < P; p++) {
                    const float* sp = slot + p * 128;
                    float4 n0 = *reinterpret_cast<const float4*>(sp + cb);
                    float4 n1 = *reinterpret_cast<const float4*>(sp + 64 + cb);
                    bt[p][0] = ffma2(dup2(n0.x), make_float2(wv0.x, wv0.y), bt[p][0]);
                    al[p][0] = ffma2(dup2(n0.x), make_float2(wv0.z, wv0.w), al[p][0]);
                    bt[p][0] = ffma2(dup2(n0.y), make_float2(wv1.x, wv1.y), bt[p][0]);
                    al[p][0] = ffma2(dup2(n0.y), make_float2(wv1.z, wv1.w), al[p][0]);
                    bt[p][0] = ffma2(dup2(n0.z), make_float2(wv2.x, wv2.y), bt[p][0]);
                    al[p][0] = ffma2(dup2(n0.z), make_float2(wv2.z, wv2.w), al[p][0]);
                    bt[p][0] = ffma2(dup2(n0.w), make_float2(wv3.x, wv3.y), bt[p][0]);
                    al[p][0] = ffma2(dup2(n0.w), make_float2(wv3.z, wv3.w), al[p][0]);
                    bt[p][1] = ffma2(dup2(n1.x), make_float2(wv0.x, wv0.y), bt[p][1]);
                    al[p][1] = ffma2(dup2(n1.x), make_float2(wv0.z, wv0.w), al[p][1]);
                    bt[p][1] = ffma2(dup2(n1.y), make_float2(wv1.x, wv1.y), bt[p][1]);
                    al[p][1] = ffma2(dup2(n1.y), make_float2(wv1.z, wv1.w), al[p][1]);
                    bt[p][1] = ffma2(dup2(n1.z), make_float2(wv2.x, wv2.y), bt[p][1]);
                    al[p][1] = ffma2(dup2(n1.z), make_float2(wv2.z, wv2.w), al[p][1]);
                    bt[p][1] = ffma2(dup2(n1.w), make_float2(wv3.x, wv3.y), bt[p][1]);
                    al[p][1] = ffma2(dup2(n1.w), make_float2(wv3.z, wv3.w), al[p][1]);
                }
            }

            // prefetch chunk t+2 into the slot we just finished reading
            if (full && t < NCHUNK - 2) {
                const int tk = (t + 2) * KB;
                #pragma unroll
                for (int r = 0; r < 8; r++) {
                    int i = lane + r * 32; int p = i >> 5, rem = i & 31;
                    cp16(nf_a + (t & 1) * 4096 + i * 16,
                         nsrc + ((size_t)p * KNB + tk) * DIM + rem * 4);
                }
                cp_commit();
            }

            __syncwarp();
            #pragma unroll
            for (int p = 0; p < P; p++) {
                #pragma unroll
                for (int ko = 0; ko < KB; ko++) {
                    const int row = (p * KB + ko) * 64;
                    betab[row + j]      = bt[p][ko].x;
                    betab[row + 32 + j] = bt[p][ko].y;
                }
            }
            __syncwarp();

            // gamma GEMM
            float2 g[P][KB];
            #pragma unroll
            for (int p = 0; p < P; p++) { g[p][0] = bg; g[p][1] = bg; }
            #pragma unroll 4
            for (int c4 = 0; c4 < 16; c4++) {
                const int cb = c4 * 4;
                float2 w0 = Wg2[(cb + 0) * 32 + j];
                float2 w1 = Wg2[(cb + 1) * 32 + j];
                float2 w2 = Wg2[(cb + 2) * 32 + j];
                float2 w3 = Wg2[(cb + 3) * 32 + j];
                #pragma unroll
                for (int p = 0; p < P; p++) {
                    const float* bp = betab + p * 128;
                    float4 b0 = *reinterpret_cast<const float4*>(bp + cb);
                    float4 b1 = *reinterpret_cast<const float4*>(bp + 64 + cb);
                    g[p][0] = ffma2(dup2(b0.x), w0, g[p][0]);
                    g[p][0] = ffma2(dup2(b0.y), w1, g[p][0]);
                    g[p][0] = ffma2(dup2(b0.z), w2, g[p][0]);
                    g[p][0] = ffma2(dup2(b0.w), w3, g[p][0]);
                    g[p][1] = ffma2(dup2(b1.x), w0, g[p][1]);
                    g[p][1] = ffma2(dup2(b1.y), w1, g[p][1]);
                    g[p][1] = ffma2(dup2(b1.z), w2, g[p][1]);
                    g[p][1] = ffma2(dup2(b1.w), w3, g[p][1]);
                }
            }

            // softmax over feature axis (values are O(0.5): no max-shift needed)
            #pragma unroll
            for (int p = 0; p < P; p++) {
                #pragma unroll
                for (int ko = 0; ko < KB; ko++) {
                    float ex = __expf(g[p][ko].x);
                    float ey = __expf(g[p][ko].y);
                    float s = ex + ey;
                    #pragma unroll
                    for (int off = 16; off > 0; off >>= 1)
                        s += __shfl_xor_sync(0xffffffffu, s, off);
                    float inv = __fdividef(1.f, s);
                    float2 e = mul2(make_float2(ex, ey), dup2(inv));
                    o[p] = ffma2(e, al[p][ko], o[p]);
                }
            }
        }

        #pragma unroll
        for (int p = 0; p < P; p++) {
            if (p < npts) {
                float* op = out + (size_t)(base + p) * DIM;
                op[j]      = o[p].x;
                op[j + 32] = o[p].y;
            }
        }
    }
}

extern "C" void kernel_launch(void* const* d_in, const int* in_sizes, int n_in,
                              void* d_out, int out_size)
{
    const float* pxyz  = (const float*)d_in[0];
    const float* pfeat = (const float*)d_in[1];
    const float* nxyz  = (const float*)d_in[2];
    const float* nfeat = (const float*)d_in[3];
    const float* Wphi  = (const float*)d_in[4];
    const float* bphi  = (const float*)d_in[5];
    const float* Wpsi  = (const float*)d_in[6];
    const float* bpsi  = (const float*)d_in[7];
    const float* Wal   = (const float*)d_in[8];
    const float* bal   = (const float*)d_in[9];
    const float* Wga   = (const float*)d_in[10];
    const float* bga   = (const float*)d_in[11];
    const float* Wd1   = (const float*)d_in[12];
    const float* bd1   = (const float*)d_in[13];
    const float* Wd2   = (const float*)d_in[14];
    const float* bd2   = (const float*)d_in[15];

    const int N = in_sizes[1] / DIM;

    int dev = 0;
    cudaGetDevice(&dev);
    int nsm = 148;
    cudaDeviceGetAttribute(&nsm, cudaDevAttrMultiProcessorCount, dev);

    void* ctr = nullptr;
    cudaGetSymbolAddress(&ctr, g_work);
    cudaMemsetAsync(ctr, 0, sizeof(int));

    cudaFuncSetAttribute(pt_layer_kernel,
                         cudaFuncAttributeMaxDynamicSharedMemorySize, SMEM_BYTES);

    pt_layer_kernel<<<nsm, THREADS, SMEM_BYTES>>>(
        pxyz, pfeat, nxyz, nfeat,
        Wphi, bphi, Wpsi, bpsi, Wal, bal, Wga, bga,
        Wd1, bd1, Wd2, bd2,
        (float*)d_out, N);
}

// round 6
// speedup vs baseline: 1.6636x; 1.6636x over previous
#include <cuda_runtime.h>
#include <cuda_fp16.h>
#include <mma.h>
#include <cstdint>

using namespace nvcuda;

// ---------------------------------------------------------------------------
// PointTransformerLayer via fp16 WMMA (HMMA, family-portable). B=1, N=50000,
// K=16, DIM=64.  Tile = 128 rows = 8 points x 16 neighbours.
//   GEMM1: nf[128x64] @ B1[64x128],  B1 = [W_alpha | W_psi@W_gamma]
//   GEMM2: delta[128x64] @ W_gamma,  delta = relu(diff@M + cv), M = Wd1@Wd2
//   gamma = D2 + fgc[p] - D1[:,64:]   (fgc = f@(W_phi@W_gamma)+c_gamma, precomp)
//   alpha = D1[:,0:64] + b_alpha + delta
//   out[p,d] = sum_k softmax_d(gamma[k,:])[d] * alpha[k,d]
// cp.async prefetch of next tile overlaps HMMA + epilogue.
// ---------------------------------------------------------------------------

constexpr int DIM     = 64;
constexpr int THREADS = 256;
constexpr int NMAX    = 50176;

constexpr int LDH = 72;   // half stride (A and B tiles)
constexpr int LD1 = 132;  // fp32 stride D1
constexpr int LD2 = 68;   // fp32 stride D2

// smem byte offsets
constexpr int RAWNF  = 0;       // 32768  next-tile nf (fp32)
constexpr int RAWFGC = 32768;   // 2048
constexpr int RAWPX  = 34816;   // 128
constexpr int RAWNX  = 34944;   // 1536
constexpr int ANFO   = 36480;   // 18432  nf fp16 [128][72]
constexpr int ADLO   = 54912;   // 18432  delta fp16 [128][72]
constexpr int B1O    = 73344;   // 18432  B1 col-major [128 cols][72]
constexpr int B2O    = 91776;   // 9216   B2 col-major [64 cols][72]
constexpr int MCVO   = 100992;  // 1024   M0,M1,M2,cv
constexpr int BALO   = 102016;  // 256
constexpr int FGCSO  = 102272;  // 2048   stable fgc tile
constexpr int SINVO  = 104320;  // 512
constexpr int D1O    = 104832;  // 67584  [128][132] fp32
constexpr int D2O    = 172416;  // 34816  [128][68]  fp32
constexpr int SMEM_BYTES = 207232;

__device__ float g_Wfg[4096];
__device__ float g_Wpg[4096];
__device__ float g_cg[64];
__device__ float g_Mcv[256];
__device__ float g_fgc[(size_t)NMAX * DIM];

// ---------------- helpers ----------------
__device__ __forceinline__ uint32_t s2u(const void* p) {
    uint32_t a;
    asm("{ .reg .u64 t; cvta.to.shared.u64 t, %1; cvt.u32.u64 %0, t; }" : "=r"(a) : "l"(p));
    return a;
}
__device__ __forceinline__ void cp16(unsigned dst, const void* src) {
    asm volatile("cp.async.cg.shared.global [%0], [%1], 16;\n" :: "r"(dst), "l"(src));
}
__device__ __forceinline__ void cp_commit() {
    asm volatile("cp.async.commit_group;\n");
}
template <int NN>
__device__ __forceinline__ void cp_wait() {
    asm volatile("cp.async.wait_group %0;\n" :: "n"(NN));
}

// ---------------- setup: fused weights ----------------
__global__ void pt_setup(const float* __restrict__ Wphi, const float* __restrict__ Wpsi,
                         const float* __restrict__ Wga,  const float* __restrict__ bphi,
                         const float* __restrict__ bpsi, const float* __restrict__ bga,
                         const float* __restrict__ Wd1,  const float* __restrict__ bd1,
                         const float* __restrict__ Wd2,  const float* __restrict__ bd2)
{
    int v = blockIdx.x * 256 + threadIdx.x;
    if (v < 8192) {
        int mat = v >> 12, idx = v & 4095, c = idx >> 6, d = idx & 63;
        const float* W = mat ? Wpsi : Wphi;
        float s = 0.f;
        #pragma unroll 8
        for (int e = 0; e < 64; e++) s = fmaf(W[c * 64 + e], Wga[e * 64 + d], s);
        if (mat) g_Wpg[idx] = s; else g_Wfg[idx] = s;
    } else if (v < 8256) {
        int d = v - 8192;
        float s = bga[d];
        for (int e = 0; e < 64; e++) s = fmaf(bphi[e] - bpsi[e], Wga[e * 64 + d], s);
        g_cg[d] = s;
    } else if (v < 8512) {
        int idx = v - 8256; int r = idx >> 6, d = idx & 63;
        float s;
        if (r < 3) {
            s = 0.f;
            for (int c = 0; c < 64; c++) s = fmaf(Wd1[r * 64 + c], Wd2[c * 64 + d], s);
        } else {
            s = bd2[d];
            for (int c = 0; c < 64; c++) s = fmaf(bd1[c], Wd2[c * 64 + d], s);
        }
        g_Mcv[idx] = s;
    }
}

// ---------------- fgc = f @ Wfg + cg ----------------
__global__ void __launch_bounds__(256)
pt_fgc(const float* __restrict__ pfeat, int N)
{
    __shared__ float sW[4096];
    __shared__ float sf[4096];
    __shared__ float scg[64];
    const int tid = threadIdx.x;
    for (int m = 0; m < 16; m++) sW[tid + 256 * m] = g_Wfg[tid + 256 * m];
    if (tid < 64) scg[tid] = g_cg[tid];
    const int i0 = blockIdx.x * 64;
    for (int m = 0; m < 16; m++) {
        int idx = tid + 256 * m; int il = idx >> 6, c = idx & 63;
        int gi = min(i0 + il, N - 1);
        sf[idx] = pfeat[(size_t)gi * 64 + c];
    }
    __syncthreads();
    for (int m = 0; m < 16; m++) {
        int v = tid + 256 * m; int il = v >> 6, d = v & 63;
        float s = scg[d];
        #pragma unroll 8
        for (int c = 0; c < 64; c++) s = fmaf(sf[il * 64 + c], sW[c * 64 + d], s);
        if (i0 + il < N) g_fgc[(size_t)(i0 + il) * 64 + d] = s;
    }
}

// ---------------- main kernel pieces ----------------
__device__ __forceinline__ void prefetch_tile(char* sm, int tile, int tid,
                                              const float* __restrict__ pxyz,
                                              const float* __restrict__ nxyz,
                                              const float* __restrict__ nfeat, int N)
{
    const long base = (long)tile * 8;
    if (base + 8 <= N) {
        const unsigned nf_a = s2u(sm + RAWNF), fg_a = s2u(sm + RAWFGC),
                       px_a = s2u(sm + RAWPX), nx_a = s2u(sm + RAWNX);
        const float* nsrc = nfeat + base * 1024;
        #pragma unroll
        for (int r = 0; r < 8; r++) { int i = tid + 256 * r; cp16(nf_a + i * 16, nsrc + i * 4); }
        if (tid < 128) cp16(fg_a + tid * 16, g_fgc + base * 64 + tid * 4);
        if (tid < 6)   cp16(px_a + tid * 16, pxyz + base * 3 + tid * 4);
        if (tid < 96)  cp16(nx_a + tid * 16, nxyz + base * 48 + tid * 4);
    } else {
        float* rnf = (float*)(sm + RAWNF);
        float* rfg = (float*)(sm + RAWFGC);
        float* rpx = (float*)(sm + RAWPX);
        float* rnx = (float*)(sm + RAWNX);
        const long lim = (long)N;
        for (int r = 0; r < 32; r++) {
            int i = tid + 256 * r;
            rnf[i] = nfeat[min(base * 1024 + i, lim * 1024 - 1)];
        }
        for (int r = 0; r < 2; r++) {
            int i = tid + 256 * r;
            rfg[i] = g_fgc[min(base * 64 + i, lim * 64 - 1)];
        }
        if (tid < 24) rpx[tid] = pxyz[min(base * 3 + tid, lim * 3 - 1)];
        for (int r = 0; r < 2; r++) {
            int i = tid + 256 * r;
            if (i < 384) rnx[i] = nxyz[min(base * 48 + i, lim * 48 - 1)];
        }
    }
    cp_commit();
}

__device__ __forceinline__ void convert_tile(char* sm, int tid)
{
    // nf fp32 -> fp16 [128][72]
    const float4* rnf = (const float4*)(sm + RAWNF);
    __half* anf = (__half*)(sm + ANFO);
    #pragma unroll
    for (int r = 0; r < 8; r++) {
        int i4 = tid + 256 * r;
        float4 v = rnf[i4];
        int e = i4 * 4, row = e >> 6, c = e & 63;
        __half2 h0 = __floats2half2_rn(v.x, v.y);
        __half2 h1 = __floats2half2_rn(v.z, v.w);
        *(uint2*)(anf + row * LDH + c) =
            make_uint2(*(uint32_t*)&h0, *(uint32_t*)&h1);
    }
    // fgc raw -> stable
    {
        float* fs = (float*)(sm + FGCSO);
        const float* rf = (const float*)(sm + RAWFGC);
        fs[tid] = rf[tid];
        fs[tid + 256] = rf[tid + 256];
    }
    // delta -> fp16 [128][72]
    {
        const float* rpx = (const float*)(sm + RAWPX);
        const float* rnx = (const float*)(sm + RAWNX);
        const float* mcv = (const float*)(sm + MCVO);
        __half* adl = (__half*)(sm + ADLO);
        const int row = tid >> 1, h = tid & 1, p = row >> 4;
        const float dx = rpx[p * 3 + 0] - rnx[row * 3 + 0];
        const float dy = rpx[p * 3 + 1] - rnx[row * 3 + 1];
        const float dz = rpx[p * 3 + 2] - rnx[row * 3 + 2];
        #pragma unroll
        for (int i4 = 0; i4 < 8; i4++) {
            const int d = h * 32 + i4 * 4;
            float4 m0 = *(const float4*)(mcv + d);
            float4 m1 = *(const float4*)(mcv + 64 + d);
            float4 m2 = *(const float4*)(mcv + 128 + d);
            float4 cv = *(const float4*)(mcv + 192 + d);
            float v0 = fmaxf(fmaf(dx, m0.x, fmaf(dy, m1.x, fmaf(dz, m2.x, cv.x))), 0.f);
            float v1 = fmaxf(fmaf(dx, m0.y, fmaf(dy, m1.y, fmaf(dz, m2.y, cv.y))), 0.f);
            float v2 = fmaxf(fmaf(dx, m0.z, fmaf(dy, m1.z, fmaf(dz, m2.z, cv.z))), 0.f);
            float v3 = fmaxf(fmaf(dx, m0.w, fmaf(dy, m1.w, fmaf(dz, m2.w, cv.w))), 0.f);
            __half2 h0 = __floats2half2_rn(v0, v1);
            __half2 h1 = __floats2half2_rn(v2, v3);
            *(uint2*)(adl + row * LDH + d) =
                make_uint2(*(uint32_t*)&h0, *(uint32_t*)&h1);
        }
    }
}

__device__ __forceinline__ void do_mma(char* sm, int warp)
{
    const __half* anf = (const __half*)(sm + ANFO);
    const __half* adl = (const __half*)(sm + ADLO);
    const __half* b1  = (const __half*)(sm + B1O);
    const __half* b2  = (const __half*)(sm + B2O);
    float* d1 = (float*)(sm + D1O);
    float* d2 = (float*)(sm + D2O);
    const int m0 = warp * 16;

    wmma::fragment<wmma::matrix_a, 16, 16, 16, __half, wmma::row_major> af;
    wmma::fragment<wmma::matrix_b, 16, 16, 16, __half, wmma::col_major> bf;
    wmma::fragment<wmma::accumulator, 16, 16, 16, float> c[8];

    #pragma unroll
    for (int j = 0; j < 8; j++) wmma::fill_fragment(c[j], 0.f);
    #pragma unroll
    for (int kk = 0; kk < 4; kk++) {
        wmma::load_matrix_sync(af, anf + m0 * LDH + kk * 16, LDH);
        #pragma unroll
        for (int j = 0; j < 8; j++) {
            wmma::load_matrix_sync(bf, b1 + j * 16 * LDH + kk * 16, LDH);
            wmma::mma_sync(c[j], af, bf, c[j]);
        }
    }
    #pragma unroll
    for (int j = 0; j < 8; j++)
        wmma::store_matrix_sync(d1 + m0 * LD1 + j * 16, c[j], LD1, wmma::mem_row_major);

    #pragma unroll
    for (int j = 0; j < 4; j++) wmma::fill_fragment(c[j], 0.f);
    #pragma unroll
    for (int kk = 0; kk < 4; kk++) {
        wmma::load_matrix_sync(af, adl + m0 * LDH + kk * 16, LDH);
        #pragma unroll
        for (int j = 0; j < 4; j++) {
            wmma::load_matrix_sync(bf, b2 + j * 16 * LDH + kk * 16, LDH);
            wmma::mma_sync(c[j], af, bf, c[j]);
        }
    }
    #pragma unroll
    for (int j = 0; j < 4; j++)
        wmma::store_matrix_sync(d2 + m0 * LD2 + j * 16, c[j], LD2, wmma::mem_row_major);
}

__device__ __forceinline__ void epilogue(char* sm, int tile, int tid,
                                         float* __restrict__ out, int N)
{
    float* d1 = (float*)(sm + D1O);
    const float* d2  = (const float*)(sm + D2O);
    const float* fgs = (const float*)(sm + FGCSO);
    const float* blv = (const float*)(sm + BALO);
    const __half* adl = (const __half*)(sm + ADLO);
    float* sinv = (float*)(sm + SINVO);

    const int r = tid >> 1, h = tid & 1, p = r >> 4;
    float* d1r = d1 + r * LD1;
    const float* d2r = d2 + r * LD2;

    float s = 0.f;
    float con[32];
    #pragma unroll
    for (int i4 = 0; i4 < 8; i4++) {
        const int d = h * 32 + i4 * 4;
        float4 ab = *(float4*)(d1r + d);
        float4 ps = *(float4*)(d1r + 64 + d);
        float4 dw = *(const float4*)(d2r + d);
        float4 fg = *(const float4*)(fgs + p * 64 + d);
        float4 bl = *(const float4*)(blv + d);
        uint2 du = *(const uint2*)(adl + r * LDH + d);
        __half2 dh0 = *(__half2*)&du.x, dh1 = *(__half2*)&du.y;
        float2 dl0 = __half22float2(dh0), dl1 = __half22float2(dh1);
        float e0 = __expf(dw.x + fg.x - ps.x); s += e0;
        float e1 = __expf(dw.y + fg.y - ps.y); s += e1;
        float e2 = __expf(dw.z + fg.z - ps.z); s += e2;
        float e3 = __expf(dw.w + fg.w - ps.w); s += e3;
        con[i4 * 4 + 0] = e0 * (ab.x + bl.x + dl0.x);
        con[i4 * 4 + 1] = e1 * (ab.y + bl.y + dl0.y);
        con[i4 * 4 + 2] = e2 * (ab.z + bl.z + dl1.x);
        con[i4 * 4 + 3] = e3 * (ab.w + bl.w + dl1.y);
    }
    float st = s + __shfl_xor_sync(0xffffffffu, s, 1);
    if (h == 0) sinv[r] = __fdividef(1.f, st);
    #pragma unroll
    for (int i4 = 0; i4 < 8; i4++) {
        const int d = h * 32 + i4 * 4;
        *(float4*)(d1r + d) = make_float4(con[i4 * 4], con[i4 * 4 + 1],
                                          con[i4 * 4 + 2], con[i4 * 4 + 3]);
    }
    __syncthreads();

    const long base = (long)tile * 8;
    #pragma unroll
    for (int m = 0; m < 2; m++) {
        int v = tid + 256 * m;
        int pp = v >> 6, dd = v & 63;
        const float* cb = d1 + (pp * 16) * LD1 + dd;
        const float* iv = sinv + pp * 16;
        float acc = 0.f;
        #pragma unroll
        for (int k = 0; k < 16; k++) acc = fmaf(cb[k * LD1], iv[k], acc);
        long gp = base + pp;
        if (gp < N) out[gp * 64 + dd] = acc;
    }
}

__global__ void __launch_bounds__(THREADS, 1)
pt_main(const float* __restrict__ pxyz, const float* __restrict__ nxyz,
        const float* __restrict__ nfeat, const float* __restrict__ Wal,
        const float* __restrict__ bal,   const float* __restrict__ Wga,
        float* __restrict__ out, int N)
{
    extern __shared__ __align__(1024) char sm[];
    const int tid = threadIdx.x, warp = tid >> 5;

    // stage constant operands (once)
    {
        __half* b1 = (__half*)(sm + B1O);
        for (int m = 0; m < 32; m++) {
            int v = tid + 256 * m; int n = v >> 6, k = v & 63;
            float w = (n < 64) ? Wal[k * 64 + n] : g_Wpg[k * 64 + (n - 64)];
            b1[n * LDH + k] = __float2half_rn(w);
        }
        __half* b2 = (__half*)(sm + B2O);
        for (int m = 0; m < 16; m++) {
            int v = tid + 256 * m; int n = v >> 6, k = v & 63;
            b2[n * LDH + k] = __float2half_rn(Wga[k * 64 + n]);
        }
        ((float*)(sm + MCVO))[tid] = g_Mcv[tid];
        if (tid < 64) ((float*)(sm + BALO))[tid] = bal[tid];
    }

    const int ntiles = (N + 7) >> 3;
    const int G = gridDim.x;
    int t = blockIdx.x;
    if (t < ntiles) prefetch_tile(sm, t, tid, pxyz, nxyz, nfeat, N);
    __syncthreads();

    for (; t < ntiles; t += G) {
        cp_wait<0>();
        __syncthreads();
        convert_tile(sm, tid);
        __syncthreads();
        if (t + G < ntiles) prefetch_tile(sm, t + G, tid, pxyz, nxyz, nfeat, N);
        do_mma(sm, warp);
        __syncthreads();
        epilogue(sm, t, tid, out, N);
        __syncthreads();
    }
}

// ---------------- launch ----------------
extern "C" void kernel_launch(void* const* d_in, const int* in_sizes, int n_in,
                              void* d_out, int out_size)
{
    const float* pxyz  = (const float*)d_in[0];
    const float* pfeat = (const float*)d_in[1];
    const float* nxyz  = (const float*)d_in[2];
    const float* nfeat = (const float*)d_in[3];
    const float* Wphi  = (const float*)d_in[4];
    const float* bphi  = (const float*)d_in[5];
    const float* Wpsi  = (const float*)d_in[6];
    const float* bpsi  = (const float*)d_in[7];
    const float* Wal   = (const float*)d_in[8];
    const float* bal   = (const float*)d_in[9];
    const float* Wga   = (const float*)d_in[10];
    const float* bga   = (const float*)d_in[11];
    const float* Wd1   = (const float*)d_in[12];
    const float* bd1   = (const float*)d_in[13];
    const float* Wd2   = (const float*)d_in[14];
    const float* bd2   = (const float*)d_in[15];

    const int N = in_sizes[1] / DIM;

    int dev = 0;
    cudaGetDevice(&dev);
    int nsm = 148;
    cudaDeviceGetAttribute(&nsm, cudaDevAttrMultiProcessorCount, dev);

    cudaFuncSetAttribute(pt_main, cudaFuncAttributeMaxDynamicSharedMemorySize, SMEM_BYTES);

    pt_setup<<<34, 256>>>(Wphi, Wpsi, Wga, bphi, bpsi, bga, Wd1, bd1, Wd2, bd2);
    pt_fgc<<<(N + 63) / 64, 256>>>(pfeat, N);

    const int ntiles = (N + 7) >> 3;
    const int grid = (ntiles < nsm) ? ntiles : nsm;
    pt_main<<<grid, THREADS, SMEM_BYTES>>>(pxyz, nxyz, nfeat, Wal, bal, Wga,
                                           (float*)d_out, N);
}

// round 8
// speedup vs baseline: 2.0119x; 1.2093x over previous
#include <cuda_runtime.h>
#include <cuda_fp16.h>
#include <mma.h>
#include <cstdint>

using namespace nvcuda;

// ---------------------------------------------------------------------------
// PointTransformerLayer via fp16 WMMA, single fused kernel. B=1, N=50000,
// K=16, DIM=64. Tile = 128 rows = 8 points x 16 neighbours.
//  Phase A (per CTA): fuse weights (Wpg=Wpsi@Wga, Wfg=Wphi@Wga, M=Wd1@Wd2, cg),
//    build fp16 B operands, compute fgc = f@Wfg + cg for THIS CTA's points via
//    WMMA and stash it in out[] (re-read in phase B, then overwritten).
//  Phase B (per tile):
//    GEMM1: nf[128x64] @ B1[64x128], B1 = [W_alpha | Wpg]
//    GEMM2: delta[128x64] @ W_gamma, delta = relu(diff@M + cv)
//    gamma = D2 + fgc - D1[:,64:], alpha = D1[:,0:64] + b_alpha + delta
//    out[p,d] = sum_k softmax_d(gamma[k,:])[d] * alpha[k,d]
//  2D MMA partition; B fragments live in registers across all tiles.
// ---------------------------------------------------------------------------

constexpr int DIM     = 64;
constexpr int THREADS = 256;

constexpr int LDH = 72;   // half stride (A/B tiles)
constexpr int LD1 = 132;  // fp32 stride D1
constexpr int LD2 = 68;   // fp32 stride D2

// smem byte offsets
constexpr int RAWNF  = 0;       // 32768  next-tile nf (fp32)
constexpr int RAWFGC = 32768;   // 2048
constexpr int RAWPX  = 34816;   // 128
constexpr int RAWNX  = 34944;   // 1536
constexpr int ANFO   = 36480;   // 18432  nf fp16 [128][72]
constexpr int ADLO   = 54912;   // 18432  delta fp16 [128][72]; WfgB in phase A
constexpr int B1O    = 73344;   // 18432  B1 col-major [128 cols][72]
constexpr int B2O    = 91776;   // 9216   B2 col-major [64 cols][72]
constexpr int MCVO   = 100992;  // 1024   M0,M1,M2,cv
constexpr int BALO   = 102016;  // 256
constexpr int FGCSO  = 102272;  // 2048   stable fgc tile
constexpr int SINVO  = 104320;  // 512
constexpr int CGO    = 104832;  // 256
constexpr int D1O    = 105088;  // 67584  [128][132] fp32 (phase-A scratch too)
constexpr int D2O    = 172672;  // 34816  [128][68]  fp32
constexpr int SMEM_BYTES = 207488;

// ---------------- helpers ----------------
__device__ __forceinline__ uint32_t s2u(const void* p) {
    uint32_t a;
    asm("{ .reg .u64 t; cvta.to.shared.u64 t, %1; cvt.u32.u64 %0, t; }" : "=r"(a) : "l"(p));
    return a;
}
__device__ __forceinline__ void cp16(unsigned dst, const void* src) {
    asm volatile("cp.async.cg.shared.global [%0], [%1], 16;\n" :: "r"(dst), "l"(src));
}
__device__ __forceinline__ void cp_commit() {
    asm volatile("cp.async.commit_group;\n");
}
template <int NN>
__device__ __forceinline__ void cp_wait() {
    asm volatile("cp.async.wait_group %0;\n" :: "n"(NN));
}

// ---------------- phase B pieces ----------------
__device__ __forceinline__ void prefetch_tile(char* sm, int tile, int tid,
                                              const float* __restrict__ pxyz,
                                              const float* __restrict__ nxyz,
                                              const float* __restrict__ nfeat,
                                              const float* __restrict__ fgc_src,
                                              int N)
{
    const long base = (long)tile * 8;
    if (base + 8 <= N) {
        const unsigned nf_a = s2u(sm + RAWNF), fg_a = s2u(sm + RAWFGC),
                       px_a = s2u(sm + RAWPX), nx_a = s2u(sm + RAWNX);
        const float* nsrc = nfeat + base * 1024;
        #pragma unroll
        for (int r = 0; r < 8; r++) { int i = tid + 256 * r; cp16(nf_a + i * 16, nsrc + i * 4); }
        if (tid < 128) cp16(fg_a + tid * 16, fgc_src + base * 64 + tid * 4);
        if (tid < 6)   cp16(px_a + tid * 16, pxyz + base * 3 + tid * 4);
        if (tid < 96)  cp16(nx_a + tid * 16, nxyz + base * 48 + tid * 4);
    } else {
        float* rnf = (float*)(sm + RAWNF);
        float* rfg = (float*)(sm + RAWFGC);
        float* rpx = (float*)(sm + RAWPX);
        float* rnx = (float*)(sm + RAWNX);
        const long lim = (long)N;
        for (int r = 0; r < 32; r++) {
            int i = tid + 256 * r;
            rnf[i] = nfeat[min(base * 1024 + i, lim * 1024 - 1)];
        }
        for (int r = 0; r < 2; r++) {
            int i = tid + 256 * r;
            rfg[i] = (base * 64 + i < lim * 64) ? fgc_src[base * 64 + i] : 0.f;
        }
        if (tid < 24) rpx[tid] = pxyz[min(base * 3 + tid, lim * 3 - 1)];
        for (int r = 0; r < 2; r++) {
            int i = tid + 256 * r;
            if (i < 384) rnx[i] = nxyz[min(base * 48 + i, lim * 48 - 1)];
        }
    }
    cp_commit();
}

__device__ __forceinline__ void convert_tile(char* sm, int tid)
{
    const float4* rnf = (const float4*)(sm + RAWNF);
    __half* anf = (__half*)(sm + ANFO);
    #pragma unroll
    for (int r = 0; r < 8; r++) {
        int i4 = tid + 256 * r;
        float4 v = rnf[i4];
        int e = i4 * 4, row = e >> 6, c = e & 63;
        __half2 h0 = __floats2half2_rn(v.x, v.y);
        __half2 h1 = __floats2half2_rn(v.z, v.w);
        *(uint2*)(anf + row * LDH + c) = make_uint2(*(uint32_t*)&h0, *(uint32_t*)&h1);
    }
    {
        float* fs = (float*)(sm + FGCSO);
        const float* rf = (const float*)(sm + RAWFGC);
        fs[tid] = rf[tid];
        fs[tid + 256] = rf[tid + 256];
    }
    {
        const float* rpx = (const float*)(sm + RAWPX);
        const float* rnx = (const float*)(sm + RAWNX);
        const float* mcv = (const float*)(sm + MCVO);
        __half* adl = (__half*)(sm + ADLO);
        const int row = tid >> 1, h = tid & 1, p = row >> 4;
        const float dx = rpx[p * 3 + 0] - rnx[row * 3 + 0];
        const float dy = rpx[p * 3 + 1] - rnx[row * 3 + 1];
        const float dz = rpx[p * 3 + 2] - rnx[row * 3 + 2];
        #pragma unroll
        for (int i4 = 0; i4 < 8; i4++) {
            const int d = h * 32 + i4 * 4;
            float4 m0 = *(const float4*)(mcv + d);
            float4 m1 = *(const float4*)(mcv + 64 + d);
            float4 m2 = *(const float4*)(mcv + 128 + d);
            float4 cv = *(const float4*)(mcv + 192 + d);
            float v0 = fmaxf(fmaf(dx, m0.x, fmaf(dy, m1.x, fmaf(dz, m2.x, cv.x))), 0.f);
            float v1 = fmaxf(fmaf(dx, m0.y, fmaf(dy, m1.y, fmaf(dz, m2.y, cv.y))), 0.f);
            float v2 = fmaxf(fmaf(dx, m0.z, fmaf(dy, m1.z, fmaf(dz, m2.z, cv.z))), 0.f);
            float v3 = fmaxf(fmaf(dx, m0.w, fmaf(dy, m1.w, fmaf(dz, m2.w, cv.w))), 0.f);
            __half2 h0 = __floats2half2_rn(v0, v1);
            __half2 h1 = __floats2half2_rn(v2, v3);
            *(uint2*)(adl + row * LDH + d) = make_uint2(*(uint32_t*)&h0, *(uint32_t*)&h1);
        }
    }
}

__device__ __forceinline__ void epilogue(char* sm, int tile, int tid,
                                         float* __restrict__ out, int N)
{
    float* d1 = (float*)(sm + D1O);
    const float* d2  = (const float*)(sm + D2O);
    const float* fgs = (const float*)(sm + FGCSO);
    const float* blv = (const float*)(sm + BALO);
    const __half* adl = (const __half*)(sm + ADLO);
    float* sinv = (float*)(sm + SINVO);

    const int r = tid >> 1, h = tid & 1, p = r >> 4;
    float* d1r = d1 + r * LD1;
    const float* d2r = d2 + r * LD2;

    float s = 0.f;
    float con[32];
    #pragma unroll
    for (int i4 = 0; i4 < 8; i4++) {
        const int d = h * 32 + i4 * 4;
        float4 ab = *(float4*)(d1r + d);
        float4 ps = *(float4*)(d1r + 64 + d);
        float4 dw = *(const float4*)(d2r + d);
        float4 fg = *(const float4*)(fgs + p * 64 + d);
        float4 bl = *(const float4*)(blv + d);
        uint2 du = *(const uint2*)(adl + r * LDH + d);
        __half2 dh0 = *(__half2*)&du.x, dh1 = *(__half2*)&du.y;
        float2 dl0 = __half22float2(dh0), dl1 = __half22float2(dh1);
        float e0 = __expf(dw.x + fg.x - ps.x); s += e0;
        float e1 = __expf(dw.y + fg.y - ps.y); s += e1;
        float e2 = __expf(dw.z + fg.z - ps.z); s += e2;
        float e3 = __expf(dw.w + fg.w - ps.w); s += e3;
        con[i4 * 4 + 0] = e0 * (ab.x + bl.x + dl0.x);
        con[i4 * 4 + 1] = e1 * (ab.y + bl.y + dl0.y);
        con[i4 * 4 + 2] = e2 * (ab.z + bl.z + dl1.x);
        con[i4 * 4 + 3] = e3 * (ab.w + bl.w + dl1.y);
    }
    float st = s + __shfl_xor_sync(0xffffffffu, s, 1);
    if (h == 0) sinv[r] = __fdividef(1.f, st);
    #pragma unroll
    for (int i4 = 0; i4 < 8; i4++) {
        const int d = h * 32 + i4 * 4;
        *(float4*)(d1r + d) = make_float4(con[i4 * 4], con[i4 * 4 + 1],
                                          con[i4 * 4 + 2], con[i4 * 4 + 3]);
    }
    __syncthreads();

    const long base = (long)tile * 8;
    #pragma unroll
    for (int m = 0; m < 2; m++) {
        int v = tid + 256 * m;
        int pp = v >> 6, dd = v & 63;
        const float* cb = d1 + (pp * 16) * LD1 + dd;
        const float* iv = sinv + pp * 16;
        float acc = 0.f;
        #pragma unroll
        for (int k = 0; k < 16; k++) acc = fmaf(cb[k * LD1], iv[k], acc);
        long gp = base + pp;
        if (gp < N) out[gp * 64 + dd] = acc;
    }
}

// ---------------- fused kernel ----------------
__global__ void __launch_bounds__(THREADS, 1)
pt_main(const float* __restrict__ pxyz,  const float* __restrict__ pfeat,
        const float* __restrict__ nxyz,  const float* __restrict__ nfeat,
        const float* __restrict__ Wphi,  const float* __restrict__ bphi,
        const float* __restrict__ Wpsi,  const float* __restrict__ bpsi,
        const float* __restrict__ Wal,   const float* __restrict__ bal,
        const float* __restrict__ Wga,   const float* __restrict__ bga,
        const float* __restrict__ Wd1,   const float* __restrict__ bd1,
        const float* __restrict__ Wd2,   const float* __restrict__ bd2,
        float* __restrict__ out, int N)
{
    extern __shared__ __align__(1024) char sm[];
    const int tid = threadIdx.x, lane = tid & 31, warp = tid >> 5;
    const int bx = blockIdx.x, G = gridDim.x;
    const int ntiles = (N + 7) >> 3;
    const int numtt = (ntiles - bx + G - 1) / G;

    __half* b1   = (__half*)(sm + B1O);
    __half* b2   = (__half*)(sm + B2O);
    __half* wfgb = (__half*)(sm + ADLO);   // phase-A overlay
    float*  cgs  = (float*)(sm + CGO);

    // ======== Phase A: weight fusion ========
    {
        float* sWga  = (float*)(sm + D1O);          // 16KB
        float* sWgaT = sWga + 4096;                 // padded stride 68
        float* sWphi = sWga + 4096 + 4352;
        float* sWpsi = sWphi + 4096;
        #pragma unroll
        for (int m = 0; m < 16; m++) {
            int i = tid + 256 * m;
            sWga[i]  = Wga[i];
            sWphi[i] = Wphi[i];
            sWpsi[i] = Wpsi[i];
        }
        __syncthreads();
        #pragma unroll
        for (int m = 0; m < 16; m++) {
            int i = tid + 256 * m; int e = i >> 6, d = i & 63;
            sWgaT[d * 68 + e] = sWga[e * 64 + d];
        }
        __syncthreads();
        // direct cols: B1 lo (W_alpha), B2 (W_gamma)
        #pragma unroll
        for (int m = 0; m < 16; m++) {
            int v = tid + 256 * m; int k = v >> 6, n = v & 63;
            b1[n * LDH + k] = __float2half_rn(Wal[k * 64 + n]);
            b2[n * LDH + k] = __float2half_rn(sWga[k * 64 + n]);
        }
        // fused cols: Wpg = Wpsi@Wga -> B1 hi; Wfg = Wphi@Wga -> wfgb
        #pragma unroll
        for (int m = 0; m < 16; m++) {
            int v = tid + 256 * m; int k = v >> 6, n = v & 63;
            const float4* pa = (const float4*)(sWpsi + k * 64);
            const float4* pb = (const float4*)(sWphi + k * 64);
            const float4* pg = (const float4*)(sWgaT + n * 68);
            float s1 = 0.f, s2 = 0.f;
            #pragma unroll
            for (int e4 = 0; e4 < 16; e4++) {
                float4 a = pa[e4], bb = pb[e4], g = pg[e4];
                s1 = fmaf(a.x, g.x, fmaf(a.y, g.y, fmaf(a.z, g.z, fmaf(a.w, g.w, s1))));
                s2 = fmaf(bb.x, g.x, fmaf(bb.y, g.y, fmaf(bb.z, g.z, fmaf(bb.w, g.w, s2))));
            }
            b1[(64 + n) * LDH + k] = __float2half_rn(s1);
            wfgb[n * LDH + k]      = __float2half_rn(s2);
        }
        if (tid < 64) {
            float s = bga[tid];
            const float* gt = sWgaT + tid * 68;
            for (int e = 0; e < 64; e++) s = fmaf(bphi[e] - bpsi[e], gt[e], s);
            cgs[tid] = s;
        }
        {
            int r = tid >> 6, d = tid & 63;
            float s;
            if (r < 3) {
                s = 0.f;
                for (int c = 0; c < 64; c++) s = fmaf(Wd1[r * 64 + c], Wd2[c * 64 + d], s);
            } else {
                s = bd2[d];
                for (int c = 0; c < 64; c++) s = fmaf(bd1[c], Wd2[c * 64 + d], s);
            }
            ((float*)(sm + MCVO))[tid] = s;
        }
        if (tid < 64) ((float*)(sm + BALO))[tid] = bal[tid];
        __syncthreads();
    }

    // ======== Phase A2: fgc = f@Wfg + cg for this CTA's points (via WMMA) ====
    {
        __half* anf = (__half*)(sm + ANFO);
        float*  fgD = (float*)(sm + D2O);
        for (int ch = 0; ch * 16 < numtt; ch++) {
            // gather f rows -> fp16 (row r = tile-in-chunk*8 + point)
            {
                const int r = tid >> 1, h = tid & 1;
                const int tt = ch * 16 + (r >> 3);
                long pt = -1;
                if (tt < numtt) {
                    long cand = (long)(bx + tt * G) * 8 + (r & 7);
                    if (cand < N) pt = cand;
                }
                #pragma unroll
                for (int i4 = 0; i4 < 8; i4++) {
                    const int c = h * 32 + i4 * 4;
                    float4 v = (pt >= 0) ? *(const float4*)(pfeat + pt * 64 + c)
                                         : make_float4(0.f, 0.f, 0.f, 0.f);
                    __half2 h0 = __floats2half2_rn(v.x, v.y);
                    __half2 h1 = __floats2half2_rn(v.z, v.w);
                    *(uint2*)(anf + r * LDH + c) =
                        make_uint2(*(uint32_t*)&h0, *(uint32_t*)&h1);
                }
            }
            __syncthreads();
            // D = A @ WfgB (128x64x64), 4 row-groups x 2 col-groups
            {
                const int r2 = warp >> 1, c2 = warp & 1;
                wmma::fragment<wmma::matrix_b, 16, 16, 16, __half, wmma::col_major> bf[2][4];
                #pragma unroll
                for (int j = 0; j < 2; j++)
                    #pragma unroll
                    for (int kk = 0; kk < 4; kk++)
                        wmma::load_matrix_sync(bf[j][kk],
                            wfgb + (c2 * 2 + j) * 16 * LDH + kk * 16, LDH);
                #pragma unroll
                for (int m = 0; m < 2; m++) {
                    const int mb = r2 * 2 + m;
                    wmma::fragment<wmma::matrix_a, 16, 16, 16, __half, wmma::row_major> af;
                    wmma::fragment<wmma::accumulator, 16, 16, 16, float> c0, c1a;
                    wmma::fill_fragment(c0, 0.f);
                    wmma::fill_fragment(c1a, 0.f);
                    #pragma unroll
                    for (int kk = 0; kk < 4; kk++) {
                        wmma::load_matrix_sync(af, anf + mb * 16 * LDH + kk * 16, LDH);
                        wmma::mma_sync(c0, af, bf[0][kk], c0);
                        wmma::mma_sync(c1a, af, bf[1][kk], c1a);
                    }
                    wmma::store_matrix_sync(fgD + mb * 16 * LD2 + (c2 * 2 + 0) * 16, c0,
                                            LD2, wmma::mem_row_major);
                    wmma::store_matrix_sync(fgD + mb * 16 * LD2 + (c2 * 2 + 1) * 16, c1a,
                                            LD2, wmma::mem_row_major);
                }
            }
            __syncthreads();
            // + cg -> out (staging for phase B): ALL 128 rows x 64 dims
            #pragma unroll
            for (int m = 0; m < 32; m++) {
                int v = tid + 256 * m;
                int r = v >> 6, d = v & 63;
                int tt = ch * 16 + (r >> 3);
                if (tt < numtt) {
                    long pt = (long)(bx + tt * G) * 8 + (r & 7);
                    if (pt < N) out[pt * 64 + d] = fgD[r * LD2 + d] + cgs[d];
                }
            }
            __syncthreads();
        }
    }

    // ======== load persistent B fragments ========
    const int c1 = warp & 3, r1 = warp >> 2;     // GEMM1: 2 rowgrp x 4 colgrp
    const int c2w = warp & 1, r2w = warp >> 1;   // GEMM2: 4 rowgrp x 2 colgrp
    wmma::fragment<wmma::matrix_b, 16, 16, 16, __half, wmma::col_major> B1f[2][4], B2f[2][4];
    #pragma unroll
    for (int j = 0; j < 2; j++)
        #pragma unroll
        for (int kk = 0; kk < 4; kk++) {
            wmma::load_matrix_sync(B1f[j][kk], b1 + (c1 * 2 + j) * 16 * LDH + kk * 16, LDH);
            wmma::load_matrix_sync(B2f[j][kk], b2 + (c2w * 2 + j) * 16 * LDH + kk * 16, LDH);
        }
    __syncthreads();

    // ======== Phase B: tile loop ========
    const __half* anf = (const __half*)(sm + ANFO);
    const __half* adl = (const __half*)(sm + ADLO);
    float* d1 = (float*)(sm + D1O);
    float* d2 = (float*)(sm + D2O);

    int t = bx;
    if (t < ntiles) prefetch_tile(sm, t, tid, pxyz, nxyz, nfeat, out, N);
    __syncthreads();

    for (; t < ntiles; t += G) {
        cp_wait<0>();
        __syncthreads();
        convert_tile(sm, tid);
        __syncthreads();
        if (t + G < ntiles) prefetch_tile(sm, t + G, tid, pxyz, nxyz, nfeat, out, N);

        // GEMM1
        #pragma unroll
        for (int m = 0; m < 4; m++) {
            const int mb = r1 * 4 + m;
            wmma::fragment<wmma::matrix_a, 16, 16, 16, __half, wmma::row_major> af;
            wmma::fragment<wmma::accumulator, 16, 16, 16, float> c0, c1a;
            wmma::fill_fragment(c0, 0.f);
            wmma::fill_fragment(c1a, 0.f);
            #pragma unroll
            for (int kk = 0; kk < 4; kk++) {
                wmma::load_matrix_sync(af, anf + mb * 16 * LDH + kk * 16, LDH);
                wmma::mma_sync(c0, af, B1f[0][kk], c0);
                wmma::mma_sync(c1a, af, B1f[1][kk], c1a);
            }
            wmma::store_matrix_sync(d1 + mb * 16 * LD1 + (c1 * 2 + 0) * 16, c0,
                                    LD1, wmma::mem_row_major);
            wmma::store_matrix_sync(d1 + mb * 16 * LD1 + (c1 * 2 + 1) * 16, c1a,
                                    LD1, wmma::mem_row_major);
        }
        // GEMM2
        #pragma unroll
        for (int m = 0; m < 2; m++) {
            const int mb = r2w * 2 + m;
            wmma::fragment<wmma::matrix_a, 16, 16, 16, __half, wmma::row_major> af;
            wmma::fragment<wmma::accumulator, 16, 16, 16, float> c0, c1a;
            wmma::fill_fragment(c0, 0.f);
            wmma::fill_fragment(c1a, 0.f);
            #pragma unroll
            for (int kk = 0; kk < 4; kk++) {
                wmma::load_matrix_sync(af, adl + mb * 16 * LDH + kk * 16, LDH);
                wmma::mma_sync(c0, af, B2f[0][kk], c0);
                wmma::mma_sync(c1a, af, B2f[1][kk], c1a);
            }
            wmma::store_matrix_sync(d2 + mb * 16 * LD2 + (c2w * 2 + 0) * 16, c0,
                                    LD2, wmma::mem_row_major);
            wmma::store_matrix_sync(d2 + mb * 16 * LD2 + (c2w * 2 + 1) * 16, c1a,
                                    LD2, wmma::mem_row_major);
        }
        __syncthreads();
        epilogue(sm, t, tid, out, N);
        __syncthreads();
    }
}

// ---------------- launch ----------------
extern "C" void kernel_launch(void* const* d_in, const int* in_sizes, int n_in,
                              void* d_out, int out_size)
{
    const float* pxyz  = (const float*)d_in[0];
    const float* pfeat = (const float*)d_in[1];
    const float* nxyz  = (const float*)d_in[2];
    const float* nfeat = (const float*)d_in[3];
    const float* Wphi  = (const float*)d_in[4];
    const float* bphi  = (const float*)d_in[5];
    const float* Wpsi  = (const float*)d_in[6];
    const float* bpsi  = (const float*)d_in[7];
    const float* Wal   = (const float*)d_in[8];
    const float* bal   = (const float*)d_in[9];
    const float* Wga   = (const float*)d_in[10];
    const float* bga   = (const float*)d_in[11];
    const float* Wd1   = (const float*)d_in[12];
    const float* bd1   = (const float*)d_in[13];
    const float* Wd2   = (const float*)d_in[14];
    const float* bd2   = (const float*)d_in[15];

    const int N = in_sizes[1] / DIM;

    int dev = 0;
    cudaGetDevice(&dev);
    int nsm = 148;
    cudaDeviceGetAttribute(&nsm, cudaDevAttrMultiProcessorCount, dev);

    cudaFuncSetAttribute(pt_main, cudaFuncAttributeMaxDynamicSharedMemorySize, SMEM_BYTES);

    const int ntiles = (N + 7) >> 3;
    const int grid = (ntiles < nsm) ? ntiles : nsm;
    pt_main<<<grid, THREADS, SMEM_BYTES>>>(pxyz, pfeat, nxyz, nfeat,
                                           Wphi, bphi, Wpsi, bpsi, Wal, bal,
                                           Wga, bga, Wd1, bd1, Wd2, bd2,
                                           (float*)d_out, N);
}

// round 9
// speedup vs baseline: 2.0175x; 1.0028x over previous
#include <cuda_runtime.h>
#include <cuda_fp16.h>
#include <mma.h>
#include <cstdint>

using namespace nvcuda;

// ---------------------------------------------------------------------------
// PointTransformerLayer via fp16 WMMA, single fused kernel. B=1, N=50000,
// K=16, DIM=64. Tile = 128 rows = 8 points x 16 neighbours.
//  Phase A (per CTA): fuse weights (Wpg=Wpsi@Wga, Wfg=Wphi@Wga, M=Wd1@Wd2, cg),
//    build fp16 B operands, compute fgc = f@Wfg + cg for THIS CTA's points via
//    WMMA and stash it in out[] (re-read in phase B, then overwritten).
//  Phase B (per tile):
//    GEMM1: nf[128x64] @ B1[64x128], B1 = [W_alpha | Wpg]
//    GEMM2: delta[128x64] @ W_gamma, delta = relu(diff@M + cv)
//    gamma = D2 + fgc - D1[:,64:], alpha = D1[:,0:64] + b_alpha + delta
//    out[p,d] = sum_k softmax_d(gamma[k,:])[d] * alpha[k,d]
//  2D MMA partition; B fragments live in registers across all tiles.
// ---------------------------------------------------------------------------

constexpr int DIM     = 64;
constexpr int THREADS = 256;

constexpr int LDH = 72;   // half stride (A/B tiles)
constexpr int LD1 = 132;  // fp32 stride D1
constexpr int LD2 = 68;   // fp32 stride D2

// smem byte offsets
constexpr int RAWNF  = 0;       // 32768  next-tile nf (fp32)
constexpr int RAWFGC = 32768;   // 2048
constexpr int RAWPX  = 34816;   // 128
constexpr int RAWNX  = 34944;   // 1536
constexpr int ANFO   = 36480;   // 18432  nf fp16 [128][72]
constexpr int ADLO   = 54912;   // 18432  delta fp16 [128][72]; WfgB in phase A
constexpr int B1O    = 73344;   // 18432  B1 col-major [128 cols][72]
constexpr int B2O    = 91776;   // 9216   B2 col-major [64 cols][72]
constexpr int MCVO   = 100992;  // 1024   M0,M1,M2,cv
constexpr int BALO   = 102016;  // 256
constexpr int FGCSO  = 102272;  // 2048   stable fgc tile
constexpr int SINVO  = 104320;  // 512
constexpr int CGO    = 104832;  // 256
constexpr int D1O    = 105088;  // 67584  [128][132] fp32 (phase-A scratch too)
constexpr int D2O    = 172672;  // 34816  [128][68]  fp32
constexpr int SMEM_BYTES = 207488;

// ---------------- helpers ----------------
__device__ __forceinline__ uint32_t s2u(const void* p) {
    uint32_t a;
    asm("{ .reg .u64 t; cvta.to.shared.u64 t, %1; cvt.u32.u64 %0, t; }" : "=r"(a) : "l"(p));
    return a;
}
__device__ __forceinline__ void cp16(unsigned dst, const void* src) {
    asm volatile("cp.async.cg.shared.global [%0], [%1], 16;\n" :: "r"(dst), "l"(src));
}
__device__ __forceinline__ void cp_commit() {
    asm volatile("cp.async.commit_group;\n");
}
template <int NN>
__device__ __forceinline__ void cp_wait() {
    asm volatile("cp.async.wait_group %0;\n" :: "n"(NN));
}

// ---------------- phase B pieces ----------------
__device__ __forceinline__ void prefetch_tile(char* sm, int tile, int tid,
                                              const float* __restrict__ pxyz,
                                              const float* __restrict__ nxyz,
                                              const float* __restrict__ nfeat,
                                              const float* __restrict__ fgc_src,
                                              int N)
{
    const long base = (long)tile * 8;
    if (base + 8 <= N) {
        const unsigned nf_a = s2u(sm + RAWNF), fg_a = s2u(sm + RAWFGC),
                       px_a = s2u(sm + RAWPX), nx_a = s2u(sm + RAWNX);
        const float* nsrc = nfeat + base * 1024;
        #pragma unroll
        for (int r = 0; r < 8; r++) { int i = tid + 256 * r; cp16(nf_a + i * 16, nsrc + i * 4); }
        if (tid < 128) cp16(fg_a + tid * 16, fgc_src + base * 64 + tid * 4);
        if (tid < 6)   cp16(px_a + tid * 16, pxyz + base * 3 + tid * 4);
        if (tid < 96)  cp16(nx_a + tid * 16, nxyz + base * 48 + tid * 4);
    } else {
        float* rnf = (float*)(sm + RAWNF);
        float* rfg = (float*)(sm + RAWFGC);
        float* rpx = (float*)(sm + RAWPX);
        float* rnx = (float*)(sm + RAWNX);
        const long lim = (long)N;
        for (int r = 0; r < 32; r++) {
            int i = tid + 256 * r;
            rnf[i] = nfeat[min(base * 1024 + i, lim * 1024 - 1)];
        }
        for (int r = 0; r < 2; r++) {
            int i = tid + 256 * r;
            rfg[i] = (base * 64 + i < lim * 64) ? fgc_src[base * 64 + i] : 0.f;
        }
        if (tid < 24) rpx[tid] = pxyz[min(base * 3 + tid, lim * 3 - 1)];
        for (int r = 0; r < 2; r++) {
            int i = tid + 256 * r;
            if (i < 384) rnx[i] = nxyz[min(base * 48 + i, lim * 48 - 1)];
        }
    }
    cp_commit();
}

__device__ __forceinline__ void convert_tile(char* sm, int tid)
{
    const float4* rnf = (const float4*)(sm + RAWNF);
    __half* anf = (__half*)(sm + ANFO);
    #pragma unroll
    for (int r = 0; r < 8; r++) {
        int i4 = tid + 256 * r;
        float4 v = rnf[i4];
        int e = i4 * 4, row = e >> 6, c = e & 63;
        __half2 h0 = __floats2half2_rn(v.x, v.y);
        __half2 h1 = __floats2half2_rn(v.z, v.w);
        *(uint2*)(anf + row * LDH + c) = make_uint2(*(uint32_t*)&h0, *(uint32_t*)&h1);
    }
    {
        float* fs = (float*)(sm + FGCSO);
        const float* rf = (const float*)(sm + RAWFGC);
        fs[tid] = rf[tid];
        fs[tid + 256] = rf[tid + 256];
    }
    {
        const float* rpx = (const float*)(sm + RAWPX);
        const float* rnx = (const float*)(sm + RAWNX);
        const float* mcv = (const float*)(sm + MCVO);
        __half* adl = (__half*)(sm + ADLO);
        const int row = tid >> 1, h = tid & 1, p = row >> 4;
        const float dx = rpx[p * 3 + 0] - rnx[row * 3 + 0];
        const float dy = rpx[p * 3 + 1] - rnx[row * 3 + 1];
        const float dz = rpx[p * 3 + 2] - rnx[row * 3 + 2];
        #pragma unroll
        for (int i4 = 0; i4 < 8; i4++) {
            const int d = h * 32 + i4 * 4;
            float4 m0 = *(const float4*)(mcv + d);
            float4 m1 = *(const float4*)(mcv + 64 + d);
            float4 m2 = *(const float4*)(mcv + 128 + d);
            float4 cv = *(const float4*)(mcv + 192 + d);
            float v0 = fmaxf(fmaf(dx, m0.x, fmaf(dy, m1.x, fmaf(dz, m2.x, cv.x))), 0.f);
            float v1 = fmaxf(fmaf(dx, m0.y, fmaf(dy, m1.y, fmaf(dz, m2.y, cv.y))), 0.f);
            float v2 = fmaxf(fmaf(dx, m0.z, fmaf(dy, m1.z, fmaf(dz, m2.z, cv.z))), 0.f);
            float v3 = fmaxf(fmaf(dx, m0.w, fmaf(dy, m1.w, fmaf(dz, m2.w, cv.w))), 0.f);
            __half2 h0 = __floats2half2_rn(v0, v1);
            __half2 h1 = __floats2half2_rn(v2, v3);
            *(uint2*)(adl + row * LDH + d) = make_uint2(*(uint32_t*)&h0, *(uint32_t*)&h1);
        }
    }
}

__device__ __forceinline__ void epilogue(char* sm, int tile, int tid,
                                         float* __restrict__ out, int N)
{
    float* d1 = (float*)(sm + D1O);
    const float* d2  = (const float*)(sm + D2O);
    const float* fgs = (const float*)(sm + FGCSO);
    const float* blv = (const float*)(sm + BALO);
    const __half* adl = (const __half*)(sm + ADLO);
    float* sinv = (float*)(sm + SINVO);

    const int r = tid >> 1, h = tid & 1, p = r >> 4;
    float* d1r = d1 + r * LD1;
    const float* d2r = d2 + r * LD2;

    float s = 0.f;
    float con[32];
    #pragma unroll
    for (int i4 = 0; i4 < 8; i4++) {
        const int d = h * 32 + i4 * 4;
        float4 ab = *(float4*)(d1r + d);
        float4 ps = *(float4*)(d1r + 64 + d);
        float4 dw = *(const float4*)(d2r + d);
        float4 fg = *(const float4*)(fgs + p * 64 + d);
        float4 bl = *(const float4*)(blv + d);
        uint2 du = *(const uint2*)(adl + r * LDH + d);
        __half2 dh0 = *(__half2*)&du.x, dh1 = *(__half2*)&du.y;
        float2 dl0 = __half22float2(dh0), dl1 = __half22float2(dh1);
        float e0 = __expf(dw.x + fg.x - ps.x); s += e0;
        float e1 = __expf(dw.y + fg.y - ps.y); s += e1;
        float e2 = __expf(dw.z + fg.z - ps.z); s += e2;
        float e3 = __expf(dw.w + fg.w - ps.w); s += e3;
        con[i4 * 4 + 0] = e0 * (ab.x + bl.x + dl0.x);
        con[i4 * 4 + 1] = e1 * (ab.y + bl.y + dl0.y);
        con[i4 * 4 + 2] = e2 * (ab.z + bl.z + dl1.x);
        con[i4 * 4 + 3] = e3 * (ab.w + bl.w + dl1.y);
    }
    float st = s + __shfl_xor_sync(0xffffffffu, s, 1);
    if (h == 0) sinv[r] = __fdividef(1.f, st);
    #pragma unroll
    for (int i4 = 0; i4 < 8; i4++) {
        const int d = h * 32 + i4 * 4;
        *(float4*)(d1r + d) = make_float4(con[i4 * 4], con[i4 * 4 + 1],
                                          con[i4 * 4 + 2], con[i4 * 4 + 3]);
    }
    __syncthreads();

    const long base = (long)tile * 8;
    #pragma unroll
    for (int m = 0; m < 2; m++) {
        int v = tid + 256 * m;
        int pp = v >> 6, dd = v & 63;
        const float* cb = d1 + (pp * 16) * LD1 + dd;
        const float* iv = sinv + pp * 16;
        float acc = 0.f;
        #pragma unroll
        for (int k = 0; k < 16; k++) acc = fmaf(cb[k * LD1], iv[k], acc);
        long gp = base + pp;
        if (gp < N) out[gp * 64 + dd] = acc;
    }
}

// ---------------- fused kernel ----------------
__global__ void __launch_bounds__(THREADS, 1)
pt_main(const float* __restrict__ pxyz,  const float* __restrict__ pfeat,
        const float* __restrict__ nxyz,  const float* __restrict__ nfeat,
        const float* __restrict__ Wphi,  const float* __restrict__ bphi,
        const float* __restrict__ Wpsi,  const float* __restrict__ bpsi,
        const float* __restrict__ Wal,   const float* __restrict__ bal,
        const float* __restrict__ Wga,   const float* __restrict__ bga,
        const float* __restrict__ Wd1,   const float* __restrict__ bd1,
        const float* __restrict__ Wd2,   const float* __restrict__ bd2,
        float* __restrict__ out, int N)
{
    extern __shared__ __align__(1024) char sm[];
    const int tid = threadIdx.x, lane = tid & 31, warp = tid >> 5;
    const int bx = blockIdx.x, G = gridDim.x;
    const int ntiles = (N + 7) >> 3;
    const int numtt = (ntiles - bx + G - 1) / G;

    __half* b1   = (__half*)(sm + B1O);
    __half* b2   = (__half*)(sm + B2O);
    __half* wfgb = (__half*)(sm + ADLO);   // phase-A overlay
    float*  cgs  = (float*)(sm + CGO);

    // ======== Phase A: weight fusion ========
    {
        float* sWga  = (float*)(sm + D1O);          // 16KB
        float* sWgaT = sWga + 4096;                 // padded stride 68
        float* sWphi = sWga + 4096 + 4352;
        float* sWpsi = sWphi + 4096;
        #pragma unroll
        for (int m = 0; m < 16; m++) {
            int i = tid + 256 * m;
            sWga[i]  = Wga[i];
            sWphi[i] = Wphi[i];
            sWpsi[i] = Wpsi[i];
        }
        __syncthreads();
        #pragma unroll
        for (int m = 0; m < 16; m++) {
            int i = tid + 256 * m; int e = i >> 6, d = i & 63;
            sWgaT[d * 68 + e] = sWga[e * 64 + d];
        }
        __syncthreads();
        // direct cols: B1 lo (W_alpha), B2 (W_gamma)
        #pragma unroll
        for (int m = 0; m < 16; m++) {
            int v = tid + 256 * m; int k = v >> 6, n = v & 63;
            b1[n * LDH + k] = __float2half_rn(Wal[k * 64 + n]);
            b2[n * LDH + k] = __float2half_rn(sWga[k * 64 + n]);
        }
        // fused cols: Wpg = Wpsi@Wga -> B1 hi; Wfg = Wphi@Wga -> wfgb
        #pragma unroll
        for (int m = 0; m < 16; m++) {
            int v = tid + 256 * m; int k = v >> 6, n = v & 63;
            const float4* pa = (const float4*)(sWpsi + k * 64);
            const float4* pb = (const float4*)(sWphi + k * 64);
            const float4* pg = (const float4*)(sWgaT + n * 68);
            float s1 = 0.f, s2 = 0.f;
            #pragma unroll
            for (int e4 = 0; e4 < 16; e4++) {
                float4 a = pa[e4], bb = pb[e4], g = pg[e4];
                s1 = fmaf(a.x, g.x, fmaf(a.y, g.y, fmaf(a.z, g.z, fmaf(a.w, g.w, s1))));
                s2 = fmaf(bb.x, g.x, fmaf(bb.y, g.y, fmaf(bb.z, g.z, fmaf(bb.w, g.w, s2))));
            }
            b1[(64 + n) * LDH + k] = __float2half_rn(s1);
            wfgb[n * LDH + k]      = __float2half_rn(s2);
        }
        if (tid < 64) {
            float s = bga[tid];
            const float* gt = sWgaT + tid * 68;
            for (int e = 0; e < 64; e++) s = fmaf(bphi[e] - bpsi[e], gt[e], s);
            cgs[tid] = s;
        }
        {
            int r = tid >> 6, d = tid & 63;
            float s;
            if (r < 3) {
                s = 0.f;
                for (int c = 0; c < 64; c++) s = fmaf(Wd1[r * 64 + c], Wd2[c * 64 + d], s);
            } else {
                s = bd2[d];
                for (int c = 0; c < 64; c++) s = fmaf(bd1[c], Wd2[c * 64 + d], s);
            }
            ((float*)(sm + MCVO))[tid] = s;
        }
        if (tid < 64) ((float*)(sm + BALO))[tid] = bal[tid];
        __syncthreads();
    }

    // ======== Phase A2: fgc = f@Wfg + cg for this CTA's points (via WMMA) ====
    {
        __half* anf = (__half*)(sm + ANFO);
        float*  fgD = (float*)(sm + D2O);
        for (int ch = 0; ch * 16 < numtt; ch++) {
            // gather f rows -> fp16 (row r = tile-in-chunk*8 + point)
            {
                const int r = tid >> 1, h = tid & 1;
                const int tt = ch * 16 + (r >> 3);
                long pt = -1;
                if (tt < numtt) {
                    long cand = (long)(bx + tt * G) * 8 + (r & 7);
                    if (cand < N) pt = cand;
                }
                #pragma unroll
                for (int i4 = 0; i4 < 8; i4++) {
                    const int c = h * 32 + i4 * 4;
                    float4 v = (pt >= 0) ? *(const float4*)(pfeat + pt * 64 + c)
                                         : make_float4(0.f, 0.f, 0.f, 0.f);
                    __half2 h0 = __floats2half2_rn(v.x, v.y);
                    __half2 h1 = __floats2half2_rn(v.z, v.w);
                    *(uint2*)(anf + r * LDH + c) =
                        make_uint2(*(uint32_t*)&h0, *(uint32_t*)&h1);
                }
            }
            __syncthreads();
            // D = A @ WfgB (128x64x64), 4 row-groups x 2 col-groups
            {
                const int r2 = warp >> 1, c2 = warp & 1;
                wmma::fragment<wmma::matrix_b, 16, 16, 16, __half, wmma::col_major> bf[2][4];
                #pragma unroll
                for (int j = 0; j < 2; j++)
                    #pragma unroll
                    for (int kk = 0; kk < 4; kk++)
                        wmma::load_matrix_sync(bf[j][kk],
                            wfgb + (c2 * 2 + j) * 16 * LDH + kk * 16, LDH);
                #pragma unroll
                for (int m = 0; m < 2; m++) {
                    const int mb = r2 * 2 + m;
                    wmma::fragment<wmma::matrix_a, 16, 16, 16, __half, wmma::row_major> af;
                    wmma::fragment<wmma::accumulator, 16, 16, 16, float> c0, c1a;
                    wmma::fill_fragment(c0, 0.f);
                    wmma::fill_fragment(c1a, 0.f);
                    #pragma unroll
                    for (int kk = 0; kk < 4; kk++) {
                        wmma::load_matrix_sync(af, anf + mb * 16 * LDH + kk * 16, LDH);
                        wmma::mma_sync(c0, af, bf[0][kk], c0);
                        wmma::mma_sync(c1a, af, bf[1][kk], c1a);
                    }
                    wmma::store_matrix_sync(fgD + mb * 16 * LD2 + (c2 * 2 + 0) * 16, c0,
                                            LD2, wmma::mem_row_major);
                    wmma::store_matrix_sync(fgD + mb * 16 * LD2 + (c2 * 2 + 1) * 16, c1a,
                                            LD2, wmma::mem_row_major);
                }
            }
            __syncthreads();
            // + cg -> out (staging for phase B): ALL 128 rows x 64 dims
            #pragma unroll
            for (int m = 0; m < 32; m++) {
                int v = tid + 256 * m;
                int r = v >> 6, d = v & 63;
                int tt = ch * 16 + (r >> 3);
                if (tt < numtt) {
                    long pt = (long)(bx + tt * G) * 8 + (r & 7);
                    if (pt < N) out[pt * 64 + d] = fgD[r * LD2 + d] + cgs[d];
                }
            }
            __syncthreads();
        }
    }

    // ======== load persistent B fragments ========
    const int c1 = warp & 3, r1 = warp >> 2;     // GEMM1: 2 rowgrp x 4 colgrp
    const int c2w = warp & 1, r2w = warp >> 1;   // GEMM2: 4 rowgrp x 2 colgrp
    wmma::fragment<wmma::matrix_b, 16, 16, 16, __half, wmma::col_major> B1f[2][4], B2f[2][4];
    #pragma unroll
    for (int j = 0; j < 2; j++)
        #pragma unroll
        for (int kk = 0; kk < 4; kk++) {
            wmma::load_matrix_sync(B1f[j][kk], b1 + (c1 * 2 + j) * 16 * LDH + kk * 16, LDH);
            wmma::load_matrix_sync(B2f[j][kk], b2 + (c2w * 2 + j) * 16 * LDH + kk * 16, LDH);
        }
    __syncthreads();

    // ======== Phase B: tile loop ========
    const __half* anf = (const __half*)(sm + ANFO);
    const __half* adl = (const __half*)(sm + ADLO);
    float* d1 = (float*)(sm + D1O);
    float* d2 = (float*)(sm + D2O);

    int t = bx;
    if (t < ntiles) prefetch_tile(sm, t, tid, pxyz, nxyz, nfeat, out, N);
    __syncthreads();

    for (; t < ntiles; t += G) {
        cp_wait<0>();
        __syncthreads();
        convert_tile(sm, tid);
        __syncthreads();
        if (t + G < ntiles) prefetch_tile(sm, t + G, tid, pxyz, nxyz, nfeat, out, N);

        // GEMM1
        #pragma unroll
        for (int m = 0; m < 4; m++) {
            const int mb = r1 * 4 + m;
            wmma::fragment<wmma::matrix_a, 16, 16, 16, __half, wmma::row_major> af;
            wmma::fragment<wmma::accumulator, 16, 16, 16, float> c0, c1a;
            wmma::fill_fragment(c0, 0.f);
            wmma::fill_fragment(c1a, 0.f);
            #pragma unroll
            for (int kk = 0; kk < 4; kk++) {
                wmma::load_matrix_sync(af, anf + mb * 16 * LDH + kk * 16, LDH);
                wmma::mma_sync(c0, af, B1f[0][kk], c0);
                wmma::mma_sync(c1a, af, B1f[1][kk], c1a);
            }
            wmma::store_matrix_sync(d1 + mb * 16 * LD1 + (c1 * 2 + 0) * 16, c0,
                                    LD1, wmma::mem_row_major);
            wmma::store_matrix_sync(d1 + mb * 16 * LD1 + (c1 * 2 + 1) * 16, c1a,
                                    LD1, wmma::mem_row_major);
        }
        // GEMM2
        #pragma unroll
        for (int m = 0; m < 2; m++) {
            const int mb = r2w * 2 + m;
            wmma::fragment<wmma::matrix_a, 16, 16, 16, __half, wmma::row_major> af;
            wmma::fragment<wmma::accumulator, 16, 16, 16, float> c0, c1a;
            wmma::fill_fragment(c0, 0.f);
            wmma::fill_fragment(c1a, 0.f);
            #pragma unroll
            for (int kk = 0; kk < 4; kk++) {
                wmma::load_matrix_sync(af, adl + mb * 16 * LDH + kk * 16, LDH);
                wmma::mma_sync(c0, af, B2f[0][kk], c0);
                wmma::mma_sync(c1a, af, B2f[1][kk], c1a);
            }
            wmma::store_matrix_sync(d2 + mb * 16 * LD2 + (c2w * 2 + 0) * 16, c0,
                                    LD2, wmma::mem_row_major);
            wmma::store_matrix_sync(d2 + mb * 16 * LD2 + (c2w * 2 + 1) * 16, c1a,
                                    LD2, wmma::mem_row_major);
        }
        __syncthreads();
        epilogue(sm, t, tid, out, N);
        __syncthreads();
    }
}

// ---------------- launch ----------------
extern "C" void kernel_launch(void* const* d_in, const int* in_sizes, int n_in,
                              void* d_out, int out_size)
{
    const float* pxyz  = (const float*)d_in[0];
    const float* pfeat = (const float*)d_in[1];
    const float* nxyz  = (const float*)d_in[2];
    const float* nfeat = (const float*)d_in[3];
    const float* Wphi  = (const float*)d_in[4];
    const float* bphi  = (const float*)d_in[5];
    const float* Wpsi  = (const float*)d_in[6];
    const float* bpsi  = (const float*)d_in[7];
    const float* Wal   = (const float*)d_in[8];
    const float* bal   = (const float*)d_in[9];
    const float* Wga   = (const float*)d_in[10];
    const float* bga   = (const float*)d_in[11];
    const float* Wd1   = (const float*)d_in[12];
    const float* bd1   = (const float*)d_in[13];
    const float* Wd2   = (const float*)d_in[14];
    const float* bd2   = (const float*)d_in[15];

    const int N = in_sizes[1] / DIM;

    int dev = 0;
    cudaGetDevice(&dev);
    int nsm = 148;
    cudaDeviceGetAttribute(&nsm, cudaDevAttrMultiProcessorCount, dev);

    cudaFuncSetAttribute(pt_main, cudaFuncAttributeMaxDynamicSharedMemorySize, SMEM_BYTES);

    const int ntiles = (N + 7) >> 3;
    const int grid = (ntiles < nsm) ? ntiles : nsm;
    pt_main<<<grid, THREADS, SMEM_BYTES>>>(pxyz, pfeat, nxyz, nfeat,
                                           Wphi, bphi, Wpsi, bpsi, Wal, bal,
                                           Wga, bga, Wd1, bd1, Wd2, bd2,
                                           (float*)d_out, N);
}